// round 15
// baseline (speedup 1.0000x reference)
#include <cuda_runtime.h>
#include <cuda_fp16.h>
#include <cuda_fp8.h>
#include <math.h>

// ---------------- problem constants ----------------
#define NC    256
#define NH    8
#define ND    32
#define KW    32
#define SW    33
#define NWIN  8192
#define NTOK  (NWIN*KW)
#define NHID  1024
#define ATT_SCALE 0.17677669529663687f
#define THREADS 256
#define WSCALE 64.0f
#define INVWS  0.015625f

// ---------------- smem pitches ----------------
#define XP  258    // post-kernel xs fp32 pitch (elements)
#define HP  264    // hs fp16 pitch (elements)
#define BP  776    // qkv fp16 pitch (elements; 33 rows, row0 = relay)
#define MP  520    // post-kernel mlp hidden fp16 pitch (elements)
#define HDB 1040   // main-kernel mlp hidden fp8 pitch (BYTES)

#define HS_BYTES   (33*HP*2)             // 17424
#define BIG_BYTES  (33*BP*2)             // 51216
#define SMEM_BYTES (HS_BYTES + BIG_BYTES)   // 68640 -> 2 CTA/SM (regs-limited)

#define PRE_SMEM   (64*HP*2)
#define POST_SMEM  (64*XP*4 + 64*HP*2 + 64*MP*2)

// ---------------- global scratch ----------------
__device__ float  g_buf_data[(size_t)NTOK * NC];
__device__ float  g_buf_rt[(size_t)NWIN * NC];
__device__ __half g_qkv_relay[(size_t)NWIN * 768];
__device__ __half g_attnout[(size_t)NWIN * NC];

// fp16 weight B-fragments, PAIR-kt layout [nt][kt/2][lane] (uint4 counts / block)
#define WP_QKV  0
#define WP_PROJ 24576
#define WP_W1   32768
#define WP_W2   65536
#define WP_BLK  98304
__device__ uint4 g_wperm[2 * WP_BLK];

// fp8 w2 B-fragments (k32), PAIR-kt layout (uint4 counts / block)
#define W2P8_BLK 16384
__device__ uint4 g_w2p8[2 * W2P8_BLK];

// rpe in mma-C-fragment layout: [blk][h][mt(2)][nt(5)][lane(32)] float4
#define RPEF_BLK 2560
__device__ float4 g_rpef[2 * RPEF_BLK];

// ---------------- helpers ----------------
__device__ __forceinline__ unsigned sm_u32(const void* p) {
    return (unsigned)__cvta_generic_to_shared(p);
}
__device__ __forceinline__ unsigned pack2h(float a, float b) {
    __half2 h = __floats2half2_rn(a, b);
    return *reinterpret_cast<unsigned*>(&h);
}
__device__ __forceinline__ unsigned char to_fp8(float x) {
    return (unsigned char)__nv_cvt_float_to_fp8(x, __NV_SATFINITE, __NV_E4M3);
}
__device__ __forceinline__ unsigned short to_fp8x2(float x, float y) {
    float2 f = make_float2(x, y);
    return (unsigned short)__nv_cvt_float2_to_fp8x2(f, __NV_SATFINITE, __NV_E4M3);
}
__device__ __forceinline__ float gelu_tanh(float x) {
    float t = 0.7978845608028654f * (x + 0.044715f * x * x * x);
    float th;
    asm("tanh.approx.f32 %0, %1;" : "=f"(th) : "f"(t));
    return 0.5f * x * (1.f + th);
}
__device__ __forceinline__ void ldmat4(unsigned a[4], unsigned addr) {
    asm volatile("ldmatrix.sync.aligned.m8n8.x4.shared.b16 {%0,%1,%2,%3}, [%4];"
                 : "=r"(a[0]), "=r"(a[1]), "=r"(a[2]), "=r"(a[3]) : "r"(addr));
}
__device__ __forceinline__ void ldmat2(unsigned& b0, unsigned& b1, unsigned addr) {
    asm volatile("ldmatrix.sync.aligned.m8n8.x2.shared.b16 {%0,%1}, [%2];"
                 : "=r"(b0), "=r"(b1) : "r"(addr));
}
__device__ __forceinline__ void ldmat2t(unsigned& b0, unsigned& b1, unsigned addr) {
    asm volatile("ldmatrix.sync.aligned.m8n8.x2.trans.shared.b16 {%0,%1}, [%2];"
                 : "=r"(b0), "=r"(b1) : "r"(addr));
}
__device__ __forceinline__ void mma_f16(float c[4], const unsigned a[4], const uint2 b) {
    asm volatile("mma.sync.aligned.m16n8k16.row.col.f32.f16.f16.f32 "
                 "{%0,%1,%2,%3},{%4,%5,%6,%7},{%8,%9},{%0,%1,%2,%3};"
                 : "+f"(c[0]), "+f"(c[1]), "+f"(c[2]), "+f"(c[3])
                 : "r"(a[0]), "r"(a[1]), "r"(a[2]), "r"(a[3]), "r"(b.x), "r"(b.y));
}
__device__ __forceinline__ void mma_fp8(float c[4], const unsigned a[4], const uint2 b) {
    asm volatile("mma.sync.aligned.m16n8k32.row.col.f32.e4m3.e4m3.f32 "
                 "{%0,%1,%2,%3},{%4,%5,%6,%7},{%8,%9},{%0,%1,%2,%3};"
                 : "+f"(c[0]), "+f"(c[1]), "+f"(c[2]), "+f"(c[3])
                 : "r"(a[0]), "r"(a[1]), "r"(a[2]), "r"(a[3]), "r"(b.x), "r"(b.y));
}

// ---------------- fused conversion kernel ----------------
__global__ void convert_all_kernel(const float* __restrict__ qkv_w,
                                   const float* __restrict__ proj_w,
                                   const float* __restrict__ w1,
                                   const float* __restrict__ w2,
                                   const float* __restrict__ rpe,
                                   uint4* __restrict__ out16,
                                   uint4* __restrict__ out8,
                                   float4* __restrict__ rpef) {
    const int N16 = 2 * WP_BLK, N8 = 2 * W2P8_BLK, NRF = 2 * RPEF_BLK;
    int idx = blockIdx.x * blockDim.x + threadIdx.x;
    if (idx < N16) {
        const int blk = idx / WP_BLK;
        int r = idx - blk * WP_BLK;
        const float* W; int K, N; int local;
        if (r < WP_PROJ)      { W = qkv_w  + (size_t)blk * 256 * 768;  K = 256;  N = 768;  local = r; }
        else if (r < WP_W1)   { W = proj_w + (size_t)blk * 256 * 256;  K = 256;  N = 256;  local = r - WP_PROJ; }
        else if (r < WP_W2)   { W = w1     + (size_t)blk * 256 * 1024; K = 256;  N = 1024; local = r - WP_W1; }
        else                  { W = w2     + (size_t)blk * 1024 * 256; K = 1024; N = 256;  local = r - WP_W2; }
        const int lane = local & 31;
        const int t    = local >> 5;
        const int KT2  = K / 32;
        const int ktp  = t % KT2, nt = t / KT2;
        const int n    = nt * 8 + (lane >> 2);
        const int kA   = (2 * ktp) * 16 + (lane & 3) * 2;
        const int kB   = kA + 16;
        uint4 v;
        v.x = pack2h(W[(size_t)kA * N + n],       W[(size_t)(kA + 1) * N + n]);
        v.y = pack2h(W[(size_t)(kA + 8) * N + n], W[(size_t)(kA + 9) * N + n]);
        v.z = pack2h(W[(size_t)kB * N + n],       W[(size_t)(kB + 1) * N + n]);
        v.w = pack2h(W[(size_t)(kB + 8) * N + n], W[(size_t)(kB + 9) * N + n]);
        out16[idx] = v;
    } else if (idx < N16 + N8) {
        int j = idx - N16;
        const int blk = j / W2P8_BLK;
        int local = j - blk * W2P8_BLK;
        const float* W = w2 + (size_t)blk * 1024 * 256;
        const int lane = local & 31;
        const int t    = local >> 5;
        const int KT2  = 16;
        const int ktp  = t % KT2, nt = t / KT2;
        const int n    = nt * 8 + (lane >> 2);
        uint4 v; unsigned* vv = (unsigned*)&v;
        #pragma unroll
        for (int half = 0; half < 2; half++) {
            const int k0 = (2 * ktp + half) * 32 + (lane & 3) * 4;
            unsigned lo = 0, hi = 0;
            #pragma unroll
            for (int i = 0; i < 4; i++) {
                lo |= (unsigned)to_fp8(W[(size_t)(k0 + i)      * 256 + n] * WSCALE) << (8 * i);
                hi |= (unsigned)to_fp8(W[(size_t)(k0 + 16 + i) * 256 + n] * WSCALE) << (8 * i);
            }
            vv[2 * half] = lo; vv[2 * half + 1] = hi;
        }
        out8[j] = v;
    } else if (idx < N16 + N8 + NRF) {
        int j = idx - N16 - N8;
        const int blk  = j / RPEF_BLK;
        int rem  = j - blk * RPEF_BLK;            // [h][mt][nt][lane]
        const int h    = rem / 320;
        rem  = rem - h * 320;
        const int mt   = rem / 160;
        const int nt   = (rem % 160) / 32;
        const int lane = rem & 31;
        const int rr   = lane >> 2, cq = (lane & 3) * 2;
        const int q0   = mt * 16 + rr + 1, q1 = q0 + 8;
        const int k0   = nt * 8 + cq,      k1 = k0 + 1;
        const float* rh = rpe + ((size_t)blk * NH + h) * SW * SW;
        float4 v;
        v.x = (k0 <= 32) ? rh[q0 * SW + k0] : 0.f;
        v.y = (k1 <= 32) ? rh[q0 * SW + k1] : 0.f;
        v.z = (k0 <= 32) ? rh[q1 * SW + k0] : 0.f;
        v.w = (k1 <= 32) ? rh[q1 * SW + k1] : 0.f;
        rpef[j] = v;
    }
}

// one marker so ncu's profiled launch (abs idx 3) = main kernel block 0
__global__ void marker_kernel() {}

// ---------------- fp16 k-outer GEMM, pair-kt uint4 B loads ----------------
template<int MODE, int KSTEPS, int NT, int MT>
__device__ __forceinline__ void do_gemm(
    const __half* __restrict__ Ash, int apitch,
    const uint4* __restrict__ wmat, int KT2tot, int nt0, int ktp0,
    const float* __restrict__ bias, const float* __restrict__ gvec,
    __half* __restrict__ outh, float* __restrict__ outf,
    int opitch, int ocol0)
{
    const int lane = threadIdx.x & 31;
    float acc[MT][NT][4];
    #pragma unroll
    for (int mt = 0; mt < MT; mt++)
        #pragma unroll
        for (int j = 0; j < NT; j++)
            #pragma unroll
            for (int e = 0; e < 4; e++) acc[mt][j][e] = 0.f;

    unsigned abase[MT];
    #pragma unroll
    for (int mt = 0; mt < MT; mt++) {
        int row = mt * 16 + (lane & 15);
        abase[mt] = sm_u32(Ash + row * apitch + ((lane >> 4) << 3));
    }
    const uint4* wb = wmat + ((size_t)nt0 * KT2tot + ktp0) * 32 + lane;

    #pragma unroll 2
    for (int ktp = 0; ktp < KSTEPS / 2; ktp++) {
        uint4 bb[NT];
        #pragma unroll
        for (int j = 0; j < NT; j++) bb[j] = __ldg(wb + ((size_t)j * KT2tot + ktp) * 32);
        unsigned a[MT][4];
        #pragma unroll
        for (int mt = 0; mt < MT; mt++) ldmat4(a[mt], abase[mt] + (unsigned)(ktp * 64));
        #pragma unroll
        for (int mt = 0; mt < MT; mt++)
            #pragma unroll
            for (int j = 0; j < NT; j++) mma_f16(acc[mt][j], a[mt], make_uint2(bb[j].x, bb[j].y));
        #pragma unroll
        for (int mt = 0; mt < MT; mt++) ldmat4(a[mt], abase[mt] + (unsigned)(ktp * 64 + 32));
        #pragma unroll
        for (int mt = 0; mt < MT; mt++)
            #pragma unroll
            for (int j = 0; j < NT; j++) mma_f16(acc[mt][j], a[mt], make_uint2(bb[j].z, bb[j].w));
    }

    const int cq = (lane & 3) * 2;
    const int rr = lane >> 2;
    #pragma unroll
    for (int j = 0; j < NT; j++) {
        const int mcol = (nt0 + j) * 8 + cq;
        const int ocol = ocol0 + j * 8 + cq;
        float b0s = 0.f, b1s = 0.f;
        if (bias) { b0s = bias[mcol]; b1s = bias[mcol + 1]; }
        float g0 = 0.f, g1 = 0.f;
        if (MODE == 2) { g0 = gvec[ocol]; g1 = gvec[ocol + 1]; }
        #pragma unroll
        for (int mt = 0; mt < MT; mt++) {
            const int r0 = mt * 16 + rr, r1 = r0 + 8;
            const float* a4 = acc[mt][j];
            const float v00 = a4[0] + b0s, v01 = a4[1] + b1s;
            const float v10 = a4[2] + b0s, v11 = a4[3] + b1s;
            if (MODE == 0) {
                *(unsigned*)(outh + r0 * opitch + ocol) = pack2h(v00, v01);
                *(unsigned*)(outh + r1 * opitch + ocol) = pack2h(v10, v11);
            } else if (MODE == 1) {
                *(unsigned*)(outh + r0 * opitch + ocol) = pack2h(gelu_tanh(v00), gelu_tanh(v01));
                *(unsigned*)(outh + r1 * opitch + ocol) = pack2h(gelu_tanh(v10), gelu_tanh(v11));
            } else {
                float* p0 = outf + r0 * opitch + ocol;
                p0[0] += g0 * v00; p0[1] += g1 * v01;
                float* p1 = outf + r1 * opitch + ocol;
                p1[0] += g0 * v10; p1[1] += g1 * v11;
            }
        }
    }
}

// ---------------- w1 GEMM: fp16 mma, gelu -> fp8 packed (MT=2) ----------------
template<int KSTEPS, int NT>
__device__ __forceinline__ void do_gemm_gelu8(
    const __half* __restrict__ Ash, int apitch,
    const uint4* __restrict__ wmat, int KT2tot, int nt0,
    const float* __restrict__ bias,
    unsigned char* __restrict__ out8, int opitchB, int ocol0)
{
    const int lane = threadIdx.x & 31;
    float acc[2][NT][4];
    #pragma unroll
    for (int mt = 0; mt < 2; mt++)
        #pragma unroll
        for (int j = 0; j < NT; j++)
            #pragma unroll
            for (int e = 0; e < 4; e++) acc[mt][j][e] = 0.f;

    unsigned abase[2];
    #pragma unroll
    for (int mt = 0; mt < 2; mt++) {
        int row = mt * 16 + (lane & 15);
        abase[mt] = sm_u32(Ash + row * apitch + ((lane >> 4) << 3));
    }
    const uint4* wb = wmat + (size_t)nt0 * KT2tot * 32 + lane;

    #pragma unroll 2
    for (int ktp = 0; ktp < KSTEPS / 2; ktp++) {
        uint4 bb[NT];
        #pragma unroll
        for (int j = 0; j < NT; j++) bb[j] = __ldg(wb + ((size_t)j * KT2tot + ktp) * 32);
        unsigned a[2][4];
        #pragma unroll
        for (int mt = 0; mt < 2; mt++) ldmat4(a[mt], abase[mt] + (unsigned)(ktp * 64));
        #pragma unroll
        for (int mt = 0; mt < 2; mt++)
            #pragma unroll
            for (int j = 0; j < NT; j++) mma_f16(acc[mt][j], a[mt], make_uint2(bb[j].x, bb[j].y));
        #pragma unroll
        for (int mt = 0; mt < 2; mt++) ldmat4(a[mt], abase[mt] + (unsigned)(ktp * 64 + 32));
        #pragma unroll
        for (int mt = 0; mt < 2; mt++)
            #pragma unroll
            for (int j = 0; j < NT; j++) mma_f16(acc[mt][j], a[mt], make_uint2(bb[j].z, bb[j].w));
    }

    const int cq = (lane & 3) * 2;
    const int rr = lane >> 2;
    #pragma unroll
    for (int j = 0; j < NT; j++) {
        const int mcol = (nt0 + j) * 8 + cq;
        const int ocol = ocol0 + j * 8 + cq;
        const float b0s = bias[mcol], b1s = bias[mcol + 1];
        #pragma unroll
        for (int mt = 0; mt < 2; mt++) {
            const int r0 = mt * 16 + rr, r1 = r0 + 8;
            const float* a4 = acc[mt][j];
            *(unsigned short*)(out8 + r0 * opitchB + ocol) =
                to_fp8x2(gelu_tanh(a4[0] + b0s), gelu_tanh(a4[1] + b1s));
            *(unsigned short*)(out8 + r1 * opitchB + ocol) =
                to_fp8x2(gelu_tanh(a4[2] + b0s), gelu_tanh(a4[3] + b1s));
        }
    }
}

// ---------------- w2 GEMM: fp8 x fp8 (k32 paired), residual epilogue ----------------
template<int KSTEPS>
__device__ __forceinline__ void do_gemm8(
    const unsigned char* __restrict__ Ash, int apitchB,
    const uint4* __restrict__ wmat, int KT2tot, int nt0,
    const float* __restrict__ bias, const float* __restrict__ gvec,
    float* __restrict__ outf, int opitch, int ocol0)
{
    const int lane = threadIdx.x & 31;
    float acc[2][4][4];
    #pragma unroll
    for (int mt = 0; mt < 2; mt++)
        #pragma unroll
        for (int j = 0; j < 4; j++)
            #pragma unroll
            for (int e = 0; e < 4; e++) acc[mt][j][e] = 0.f;

    unsigned abase[2];
    #pragma unroll
    for (int mt = 0; mt < 2; mt++) {
        int row = mt * 16 + (lane & 15);
        abase[mt] = sm_u32(Ash + row * apitchB + ((lane >> 4) << 4));
    }
    const uint4* wb = wmat + (size_t)nt0 * KT2tot * 32 + lane;

    #pragma unroll 2
    for (int ktp = 0; ktp < KSTEPS / 2; ktp++) {
        uint4 bb[4];
        #pragma unroll
        for (int j = 0; j < 4; j++) bb[j] = __ldg(wb + ((size_t)j * KT2tot + ktp) * 32);
        unsigned a[2][4];
        #pragma unroll
        for (int mt = 0; mt < 2; mt++) ldmat4(a[mt], abase[mt] + (unsigned)(ktp * 64));
        #pragma unroll
        for (int mt = 0; mt < 2; mt++)
            #pragma unroll
            for (int j = 0; j < 4; j++) mma_fp8(acc[mt][j], a[mt], make_uint2(bb[j].x, bb[j].y));
        #pragma unroll
        for (int mt = 0; mt < 2; mt++) ldmat4(a[mt], abase[mt] + (unsigned)(ktp * 64 + 32));
        #pragma unroll
        for (int mt = 0; mt < 2; mt++)
            #pragma unroll
            for (int j = 0; j < 4; j++) mma_fp8(acc[mt][j], a[mt], make_uint2(bb[j].z, bb[j].w));
    }

    const int cq = (lane & 3) * 2;
    const int rr = lane >> 2;
    #pragma unroll
    for (int j = 0; j < 4; j++) {
        const int mcol = (nt0 + j) * 8 + cq;
        const int ocol = ocol0 + j * 8 + cq;
        const float b0s = bias[mcol], b1s = bias[mcol + 1];
        const float g0 = gvec[ocol], g1 = gvec[ocol + 1];
        #pragma unroll
        for (int mt = 0; mt < 2; mt++) {
            const int r0 = mt * 16 + rr, r1 = r0 + 8;
            const float* a4 = acc[mt][j];
            float* p0 = outf + r0 * opitch + ocol;
            p0[0] += g0 * fmaf(a4[0], INVWS, b0s);
            p0[1] += g1 * fmaf(a4[1], INVWS, b1s);
            float* p1 = outf + r1 * opitch + ocol;
            p1[0] += g0 * fmaf(a4[2], INVWS, b0s);
            p1[1] += g1 * fmaf(a4[3], INVWS, b1s);
        }
    }
}

// hfma2 dot: 16 half2 pairs -> fp32 scalar (relay path)
__device__ __forceinline__ float dot32_h2(const __half2* a, const __half2* b) {
    __half2 acc0 = __hmul2(a[0], b[0]);
    __half2 acc1 = __hmul2(a[1], b[1]);
    #pragma unroll
    for (int i = 2; i < 16; i += 2) {
        acc0 = __hfma2(a[i],     b[i],     acc0);
        acc1 = __hfma2(a[i + 1], b[i + 1], acc1);
    }
    __half2 acc = __hadd2(acc0, acc1);
    return __half2float(__low2half(acc)) + __half2float(__high2half(acc));
}

// LN rows helper for 64-row pre/post tiles
__device__ __forceinline__ void ln_rows64(
    const float* __restrict__ X, int xpitch, __half* __restrict__ Out,
    const float* __restrict__ g, const float* __restrict__ b)
{
    const int wq = threadIdx.x >> 5, lane = threadIdx.x & 31;
    for (int row = wq; row < 64; row += 8) {
        const float* rp = X + row * xpitch;
        float sum = 0.f, sum2 = 0.f;
        #pragma unroll
        for (int c = lane; c < NC; c += 32) { float v = rp[c]; sum += v; sum2 += v * v; }
        #pragma unroll
        for (int o = 16; o; o >>= 1) {
            sum  += __shfl_xor_sync(0xffffffffu, sum, o);
            sum2 += __shfl_xor_sync(0xffffffffu, sum2, o);
        }
        const float m    = sum * (1.f / NC);
        const float var  = fmaxf(sum2 * (1.f / NC) - m * m, 0.f);
        const float rstd = rsqrtf(var + 1e-5f);
        #pragma unroll
        for (int c = lane; c < NC; c += 32)
            Out[row * HP + c] = __float2half_rn((rp[c] - m) * rstd * g[c] + b[c]);
    }
}

// ---------------- pre kernel: relay LN1 + qkv (block 0 only) ----------------
__global__ void __launch_bounds__(THREADS, 1)
pre_kernel(const float* __restrict__ rt_in, const uint4* __restrict__ wqkv,
           const float* __restrict__ ln1_g, const float* __restrict__ ln1_b,
           const float* __restrict__ qkv_b, __half* __restrict__ qkv_relay)
{
    extern __shared__ char sm8[];
    __half* hs = (__half*)sm8;
    const int tid = threadIdx.x, wq = tid >> 5, lane = tid & 31;
    const int r0 = blockIdx.x * 64;

    for (int row = wq; row < 64; row += 8) {
        const float* rp = rt_in + (size_t)(r0 + row) * NC;
        float v[8], sum = 0.f, sum2 = 0.f;
        #pragma unroll
        for (int i = 0; i < 8; i++) {
            v[i] = rp[lane + 32 * i];
            sum += v[i]; sum2 += v[i] * v[i];
        }
        #pragma unroll
        for (int o = 16; o; o >>= 1) {
            sum  += __shfl_xor_sync(0xffffffffu, sum, o);
            sum2 += __shfl_xor_sync(0xffffffffu, sum2, o);
        }
        const float m    = sum * (1.f / NC);
        const float var  = fmaxf(sum2 * (1.f / NC) - m * m, 0.f);
        const float rstd = rsqrtf(var + 1e-5f);
        #pragma unroll
        for (int i = 0; i < 8; i++) {
            const int c = lane + 32 * i;
            hs[row * HP + c] = __float2half_rn((v[i] - m) * rstd * ln1_g[c] + ln1_b[c]);
        }
    }
    __syncthreads();

    __half* outg = qkv_relay + (size_t)r0 * 768;
    #pragma unroll 1
    for (int p = 0; p < 2; p++) {
        const int nt = wq * 12 + p * 6;
        do_gemm<0, 16, 6, 4>(hs, HP, wqkv, 8, nt, 0, qkv_b, nullptr,
                             outg, nullptr, 768, nt * 8);
    }
}

// ---------------- post kernel: relay proj+LN2+MLP (+ fused next-block pre) ----------------
__global__ void __launch_bounds__(THREADS, 1)
post_kernel(const float* __restrict__ rt_in, const __half* __restrict__ attnout,
            const uint4* __restrict__ wproj, const uint4* __restrict__ w1p,
            const uint4* __restrict__ w2p,
            const float* __restrict__ proj_b,
            const float* __restrict__ ln2_g, const float* __restrict__ ln2_b,
            const float* __restrict__ b1,   const float* __restrict__ b2,
            const float* __restrict__ gamma1, const float* __restrict__ gamma2,
            float* __restrict__ out_rt,
            const uint4* __restrict__ wqkv_n,
            const float* __restrict__ ln1_g_n, const float* __restrict__ ln1_b_n,
            const float* __restrict__ qkv_b_n, __half* __restrict__ qkv_relay_n)
{
    extern __shared__ char sm8[];
    float*  xs  = (float*)sm8;
    __half* hs  = (__half*)(sm8 + 64 * XP * 4);
    __half* hid = (__half*)(sm8 + 64 * XP * 4 + 64 * HP * 2);
    const int tid = threadIdx.x, wq = tid >> 5, lane = tid & 31;
    const int r0 = blockIdx.x * 64;

    for (int idx = tid; idx < 64 * NC; idx += THREADS) {
        const int row = idx >> 8, c = idx & 255;
        xs[row * XP + c] = rt_in[(size_t)(r0 + row) * NC + c];
        hs[row * HP + c] = attnout[(size_t)(r0 + row) * NC + c];
    }
    __syncthreads();

    do_gemm<2, 16, 4, 4>(hs, HP, wproj, 8, wq * 4, 0, proj_b, gamma1,
                         nullptr, xs, XP, wq * 32);
    __syncthreads();

    ln_rows64(xs, XP, hs, ln2_g, ln2_b);
    __syncthreads();

    #pragma unroll 1
    for (int c = 0; c < 2; c++) {
        #pragma unroll 1
        for (int p = 0; p < 2; p++) {
            const int nt = c * 64 + wq * 8 + p * 4;
            do_gemm<1, 16, 4, 4>(hs, HP, w1p, 8, nt, 0, b1, nullptr,
                                 hid, nullptr, MP, nt * 8 - c * 512);
        }
        __syncthreads();
        do_gemm<2, 32, 4, 4>(hid, MP, w2p, 32, wq * 4, c * 16,
                             (c == 0) ? b2 : nullptr, gamma2, nullptr, xs, XP, wq * 32);
        __syncthreads();
    }

    for (int idx = tid; idx < 64 * NC; idx += THREADS) {
        const int row = idx >> 8, c = idx & 255;
        out_rt[(size_t)(r0 + row) * NC + c] = xs[row * XP + c];
    }

    // ---- fused pre of next block: LN1(new rt) + qkv ----
    if (wqkv_n) {
        __syncthreads();
        ln_rows64(xs, XP, hs, ln1_g_n, ln1_b_n);
        __syncthreads();
        __half* outg = qkv_relay_n + (size_t)r0 * 768;
        #pragma unroll 1
        for (int p = 0; p < 2; p++) {
            const int nt = wq * 12 + p * 6;
            do_gemm<0, 16, 6, 4>(hs, HP, wqkv_n, 8, nt, 0, qkv_b_n, nullptr,
                                 outg, nullptr, 768, nt * 8);
        }
    }
}

// ---------------- main fused window kernel (32 data rows, resid in GMEM) ----------------
__global__ void __launch_bounds__(THREADS, 2)
hot_block_kernel(
    const float* __restrict__ in_data,
    const uint4* __restrict__ wp,     const uint4* __restrict__ w2p8,
    const float4* __restrict__ rpef,  const float* __restrict__ rpe0,
    const __half* __restrict__ qkv_relay, __half* __restrict__ attnout,
    const float* __restrict__ cpe_w,  const float* __restrict__ cpe_b,
    const float* __restrict__ ln1_g,  const float* __restrict__ ln1_b,
    const float* __restrict__ qkv_b,
    const float* __restrict__ proj_b,
    const float* __restrict__ ln2_g,  const float* __restrict__ ln2_b,
    const float* __restrict__ b1,     const float* __restrict__ b2,
    const float* __restrict__ gamma1, const float* __restrict__ gamma2,
    float* __restrict__ resid)        // residual stream buffer == output data layout
{
    extern __shared__ char sm8[];
    __half* hs  = (__half*)sm8;                         // [33][264] (row0 unused)
    __half* big = (__half*)(sm8 + HS_BYTES);            // [33][776] qkv
    unsigned char* hid8 = (unsigned char*)big;          // fp8 hidden [32][1040B] overlays

    const int tid  = threadIdx.x;
    const int wq   = tid >> 5;
    const int lane = tid & 31;
    const int w    = blockIdx.x;

    const uint4* wqkv  = wp + WP_QKV;
    const uint4* wproj = wp + WP_PROJ;
    const uint4* w1p   = wp + WP_W1;

    float* resid_w = resid + (size_t)w * KW * NC;       // [32][256] fp32 in gmem

    // ---- Phase A: cpe + LN1 fused (vectorized, x -> resid gmem) + relay qkv load ----
    {
        const int c0 = lane * 8;
        for (int s = 1 + wq; s < SW; s += 8) {
            const long r = (long)w * KW + (s - 1);
            const float* row0 = in_data + r * NC + c0;
            float4 xa = *(const float4*)row0;
            float4 xb = *(const float4*)(row0 + 4);
            float4 ma, mb, pa, pb;
            if (r > 0) { ma = *(const float4*)(row0 - NC); mb = *(const float4*)(row0 - NC + 4); }
            else       { ma = make_float4(0,0,0,0); mb = ma; }
            if (r < NTOK - 1) { pa = *(const float4*)(row0 + NC); pb = *(const float4*)(row0 + NC + 4); }
            else       { pa = make_float4(0,0,0,0); pb = pa; }
            const float4 c0a = *(const float4*)(cpe_w + c0),          c0b = *(const float4*)(cpe_w + c0 + 4);
            const float4 c1a = *(const float4*)(cpe_w + NC + c0),     c1b = *(const float4*)(cpe_w + NC + c0 + 4);
            const float4 c2a = *(const float4*)(cpe_w + 2*NC + c0),   c2b = *(const float4*)(cpe_w + 2*NC + c0 + 4);
            const float4 cba = *(const float4*)(cpe_b + c0),          cbb = *(const float4*)(cpe_b + c0 + 4);
            float v[8];
            v[0] = xa.x + ma.x*c0a.x + xa.x*c1a.x + pa.x*c2a.x + cba.x;
            v[1] = xa.y + ma.y*c0a.y + xa.y*c1a.y + pa.y*c2a.y + cba.y;
            v[2] = xa.z + ma.z*c0a.z + xa.z*c1a.z + pa.z*c2a.z + cba.z;
            v[3] = xa.w + ma.w*c0a.w + xa.w*c1a.w + pa.w*c2a.w + cba.w;
            v[4] = xb.x + mb.x*c0b.x + xb.x*c1b.x + pb.x*c2b.x + cbb.x;
            v[5] = xb.y + mb.y*c0b.y + xb.y*c1b.y + pb.y*c2b.y + cbb.y;
            v[6] = xb.z + mb.z*c0b.z + xb.z*c1b.z + pb.z*c2b.z + cbb.z;
            v[7] = xb.w + mb.w*c0b.w + xb.w*c1b.w + pb.w*c2b.w + cbb.w;
            float sum = 0.f, sum2 = 0.f;
            #pragma unroll
            for (int i = 0; i < 8; i++) { sum += v[i]; sum2 += v[i]*v[i]; }
            #pragma unroll
            for (int o = 16; o; o >>= 1) {
                sum  += __shfl_xor_sync(0xffffffffu, sum, o);
                sum2 += __shfl_xor_sync(0xffffffffu, sum2, o);
            }
            const float m    = sum * (1.f / NC);
            const float var  = fmaxf(sum2 * (1.f / NC) - m * m, 0.f);
            const float rstd = rsqrtf(var + 1e-5f);
            float* rw = resid_w + (s - 1) * NC + c0;
            *(float4*)rw       = make_float4(v[0], v[1], v[2], v[3]);
            *(float4*)(rw + 4) = make_float4(v[4], v[5], v[6], v[7]);
            const float4 ga = *(const float4*)(ln1_g + c0), gb = *(const float4*)(ln1_g + c0 + 4);
            const float4 ba = *(const float4*)(ln1_b + c0), bb4 = *(const float4*)(ln1_b + c0 + 4);
            unsigned hh[4];
            hh[0] = pack2h((v[0]-m)*rstd*ga.x + ba.x,  (v[1]-m)*rstd*ga.y + ba.y);
            hh[1] = pack2h((v[2]-m)*rstd*ga.z + ba.z,  (v[3]-m)*rstd*ga.w + ba.w);
            hh[2] = pack2h((v[4]-m)*rstd*gb.x + bb4.x, (v[5]-m)*rstd*gb.y + bb4.y);
            hh[3] = pack2h((v[6]-m)*rstd*gb.z + bb4.z, (v[7]-m)*rstd*gb.w + bb4.w);
            *(uint4*)(hs + s * HP + c0) = *(uint4*)hh;
        }
    }
    {   // relay qkv -> big row 0
        const unsigned* src = (const unsigned*)(qkv_relay + (size_t)w * 768);
        unsigned* dst = (unsigned*)big;
        for (int idx = tid; idx < 384; idx += THREADS) dst[idx] = src[idx];
    }
    __syncthreads();

    // ---- Phase C: qkv (data rows) -> big rows 1..32 ----
    #pragma unroll 1
    for (int p = 0; p < 2; p++) {
        const int nt = wq * 12 + p * 6;
        do_gemm<0, 16, 6, 2>(hs + HP, HP, wqkv, 8, nt, 0, qkv_b, nullptr,
                             big + BP, nullptr, BP, nt * 8);
    }
    __syncthreads();

    // ---- Phase D: attention via tensor cores (warp = head) ----
    {
        const int h  = wq;
        const int rr = lane >> 2, cq = (lane & 3) * 2;
        const int L  = lane & 15;

        uint2 bk[5][2];
        #pragma unroll
        for (int nt = 0; nt < 5; nt++) {
            int key = nt * 8 + (L & 7); if (key > 32) key = 32;
            #pragma unroll
            for (int kt = 0; kt < 2; kt++)
                ldmat2(bk[nt][kt].x, bk[nt][kt].y,
                       sm_u32(big + key * BP + 256 + h * ND + kt * 16 + ((L >> 3) << 3)));
        }

        float accS[2][5][4];
        #pragma unroll
        for (int mt = 0; mt < 2; mt++)
            #pragma unroll
            for (int nt = 0; nt < 5; nt++)
                #pragma unroll
                for (int e = 0; e < 4; e++) accS[mt][nt][e] = 0.f;
        #pragma unroll
        for (int mt = 0; mt < 2; mt++) {
            #pragma unroll
            for (int kt = 0; kt < 2; kt++) {
                unsigned aq[4];
                ldmat4(aq, sm_u32(big + (1 + mt * 16 + L) * BP + h * ND
                                  + ((lane >> 4) << 3) + kt * 16));
                #pragma unroll
                for (int nt = 0; nt < 5; nt++) mma_f16(accS[mt][nt], aq, bk[nt][kt]);
            }
        }

        const float4* rpef_h = rpef + h * 320;
        float sum0[2], sum1[2];
        unsigned ap[2][3][4];
        #pragma unroll
        for (int mt = 0; mt < 2; mt++) {
            float p[5][4];
            float s0 = 0.f, s1 = 0.f;
            #pragma unroll
            for (int nt = 0; nt < 5; nt++) {
                const float4 rv = rpef_h[(mt * 5 + nt) * 32 + lane];
                float e0 = __expf(fmaf(accS[mt][nt][0], ATT_SCALE, rv.x));
                float e1 = __expf(fmaf(accS[mt][nt][1], ATT_SCALE, rv.y));
                float e2 = __expf(fmaf(accS[mt][nt][2], ATT_SCALE, rv.z));
                float e3 = __expf(fmaf(accS[mt][nt][3], ATT_SCALE, rv.w));
                if (nt == 4) {
                    const bool vld = (cq == 0);
                    e0 = vld ? e0 : 0.f; e2 = vld ? e2 : 0.f;
                    e1 = 0.f; e3 = 0.f;
                }
                p[nt][0] = e0; p[nt][1] = e1; p[nt][2] = e2; p[nt][3] = e3;
                s0 += e0 + e1; s1 += e2 + e3;
            }
            s0 += __shfl_xor_sync(0xffffffffu, s0, 1);
            s0 += __shfl_xor_sync(0xffffffffu, s0, 2);
            s1 += __shfl_xor_sync(0xffffffffu, s1, 1);
            s1 += __shfl_xor_sync(0xffffffffu, s1, 2);
            sum0[mt] = s0; sum1[mt] = s1;
            #pragma unroll
            for (int s = 0; s < 3; s++) {
                const int n0 = 2 * s, n1 = 2 * s + 1;
                ap[mt][s][0] = pack2h(p[n0][0], p[n0][1]);
                ap[mt][s][1] = pack2h(p[n0][2], p[n0][3]);
                ap[mt][s][2] = (n1 < 5) ? pack2h(p[n1][0], p[n1][1]) : 0u;
                ap[mt][s][3] = (n1 < 5) ? pack2h(p[n1][2], p[n1][3]) : 0u;
            }
        }

        float accO[2][4][4];
        #pragma unroll
        for (int mt = 0; mt < 2; mt++)
            #pragma unroll
            for (int nt = 0; nt < 4; nt++)
                #pragma unroll
                for (int e = 0; e < 4; e++) accO[mt][nt][e] = 0.f;
        #pragma unroll
        for (int kt = 0; kt < 3; kt++) {
            int key = kt * 16 + L; if (key > 32) key = 32;
            uint2 bv[4];
            #pragma unroll
            for (int nt = 0; nt < 4; nt++)
                ldmat2t(bv[nt].x, bv[nt].y,
                        sm_u32(big + key * BP + 512 + h * ND + nt * 8));
            #pragma unroll
            for (int mt = 0; mt < 2; mt++)
                #pragma unroll
                for (int nt = 0; nt < 4; nt++) mma_f16(accO[mt][nt], ap[mt][kt], bv[nt]);
        }

        #pragma unroll
        for (int mt = 0; mt < 2; mt++) {
            const float i0 = 1.f / sum0[mt], i1 = 1.f / sum1[mt];
            #pragma unroll
            for (int nt = 0; nt < 4; nt++) {
                const int d = nt * 8 + cq;
                *(unsigned*)(hs + (1 + mt * 16 + rr) * HP + h * ND + d) =
                    pack2h(accO[mt][nt][0] * i0, accO[mt][nt][1] * i0);
                *(unsigned*)(hs + (9 + mt * 16 + rr) * HP + h * ND + d) =
                    pack2h(accO[mt][nt][2] * i1, accO[mt][nt][3] * i1);
            }
        }

        // relay query (ref q = 0): scalar path
        const float* rp0 = rpe0 + h * SW * SW;
        __half2 q0h[16], kh[16];
        {
            const uint4* qp = (const uint4*)(big + h * ND);
            #pragma unroll
            for (int i = 0; i < 4; i++) ((uint4*)q0h)[i] = qp[i];
        }
        {
            const uint4* kp = (const uint4*)(big + lane * BP + 256 + h * ND);
            #pragma unroll
            for (int i = 0; i < 4; i++) ((uint4*)kh)[i] = kp[i];
        }
        float e = __expf(fmaf(dot32_h2(q0h, kh), ATT_SCALE, rp0[lane]));
        {
            const uint4* kp = (const uint4*)(big + 32 * BP + 256 + h * ND);
            #pragma unroll
            for (int i = 0; i < 4; i++) ((uint4*)kh)[i] = kp[i];
        }
        const float e32 = __expf(fmaf(dot32_h2(q0h, kh), ATT_SCALE, rp0[32]));
        float d = e;
        #pragma unroll
        for (int o = 16; o; o >>= 1) d += __shfl_xor_sync(0xffffffffu, d, o);
        d += e32;
        const float invd = 1.f / d;
        const float pr   = e * invd;
        float o = (e32 * invd) * __half2float(big[32 * BP + 512 + h * ND + lane]);
        #pragma unroll 4
        for (int k = 0; k < 32; k++) {
            const float pk = __shfl_sync(0xffffffffu, pr, k);
            o = fmaf(pk, __half2float(big[k * BP + 512 + h * ND + lane]), o);
        }
        attnout[(size_t)w * NC + h * ND + lane] = __float2half_rn(o);
    }
    __syncthreads();

    // ---- Phase E: resid += gamma1 * (o @ proj_w + proj_b)  (gmem RMW) ----
    do_gemm<2, 16, 4, 2>(hs + HP, HP, wproj, 8, wq * 4, 0, proj_b, gamma1,
                         nullptr, resid_w, NC, wq * 32);
    __syncthreads();

    // ---- Phase F: LN2 (read resid gmem, vectorized) ----
    {
        const int c0 = lane * 8;
        for (int s = 1 + wq; s < SW; s += 8) {
            const float* rp = resid_w + (s - 1) * NC + c0;
            const float4 va = *(const float4*)rp;
            const float4 vb = *(const float4*)(rp + 4);
            float sum  = va.x + va.y + va.z + va.w + vb.x + vb.y + vb.z + vb.w;
            float sum2 = va.x*va.x + va.y*va.y + va.z*va.z + va.w*va.w
                       + vb.x*vb.x + vb.y*vb.y + vb.z*vb.z + vb.w*vb.w;
            #pragma unroll
            for (int o = 16; o; o >>= 1) {
                sum  += __shfl_xor_sync(0xffffffffu, sum, o);
                sum2 += __shfl_xor_sync(0xffffffffu, sum2, o);
            }
            const float m    = sum * (1.f / NC);
            const float var  = fmaxf(sum2 * (1.f / NC) - m * m, 0.f);
            const float rstd = rsqrtf(var + 1e-5f);
            const float4 ga = *(const float4*)(ln2_g + c0), gb = *(const float4*)(ln2_g + c0 + 4);
            const float4 ba = *(const float4*)(ln2_b + c0), bb4 = *(const float4*)(ln2_b + c0 + 4);
            unsigned hh[4];
            hh[0] = pack2h((va.x-m)*rstd*ga.x + ba.x,  (va.y-m)*rstd*ga.y + ba.y);
            hh[1] = pack2h((va.z-m)*rstd*ga.z + ba.z,  (va.w-m)*rstd*ga.w + ba.w);
            hh[2] = pack2h((vb.x-m)*rstd*gb.x + bb4.x, (vb.y-m)*rstd*gb.y + bb4.y);
            hh[3] = pack2h((vb.z-m)*rstd*gb.z + bb4.z, (vb.w-m)*rstd*gb.w + bb4.w);
            *(uint4*)(hs + s * HP + c0) = *(uint4*)hh;
        }
    }
    __syncthreads();

    // ---- Phase G: MLP single-pass, hidden fp8 [32][1040B]; w2 epilogue -> resid gmem ----
    #pragma unroll 1
    for (int p = 0; p < 2; p++) {
        const int nt = wq * 16 + p * 8;
        do_gemm_gelu8<16, 8>(hs + HP, HP, w1p, 8, nt, b1, hid8, HDB, nt * 8);
    }
    __syncthreads();
    do_gemm8<32>(hid8, HDB, w2p8, 16, wq * 4, b2, gamma2, resid_w, NC, wq * 32);
    // resid_w now holds the final output rows — no Phase H.
}

// ---------------- host launch ----------------
extern "C" void kernel_launch(void* const* d_in, const int* in_sizes, int n_in,
                              void* d_out, int out_size) {
    (void)in_sizes; (void)n_in; (void)out_size;
    const float* data   = (const float*)d_in[0];
    const float* rt     = (const float*)d_in[1];
    const float* cpe_w  = (const float*)d_in[2];
    const float* cpe_b  = (const float*)d_in[3];
    const float* ln1_g  = (const float*)d_in[4];
    const float* ln1_b  = (const float*)d_in[5];
    const float* qkv_w  = (const float*)d_in[6];
    const float* qkv_b  = (const float*)d_in[7];
    const float* rpe    = (const float*)d_in[8];
    const float* proj_w = (const float*)d_in[9];
    const float* proj_b = (const float*)d_in[10];
    const float* ln2_g  = (const float*)d_in[11];
    const float* ln2_b  = (const float*)d_in[12];
    const float* w1     = (const float*)d_in[13];
    const float* b1     = (const float*)d_in[14];
    const float* w2     = (const float*)d_in[15];
    const float* b2     = (const float*)d_in[16];
    const float* gamma1 = (const float*)d_in[17];
    const float* gamma2 = (const float*)d_in[18];

    float* out_data = (float*)d_out;
    float* out_rt   = out_data + (size_t)NTOK * NC;

    cudaFuncSetAttribute(hot_block_kernel,
                         cudaFuncAttributeMaxDynamicSharedMemorySize, SMEM_BYTES);
    cudaFuncSetAttribute(pre_kernel,
                         cudaFuncAttributeMaxDynamicSharedMemorySize, PRE_SMEM);
    cudaFuncSetAttribute(post_kernel,
                         cudaFuncAttributeMaxDynamicSharedMemorySize, POST_SMEM);

    float *bd, *brt;
    cudaGetSymbolAddress((void**)&bd,  g_buf_data);
    cudaGetSymbolAddress((void**)&brt, g_buf_rt);
    uint4 *wpall, *w2p8;
    cudaGetSymbolAddress((void**)&wpall, g_wperm);
    cudaGetSymbolAddress((void**)&w2p8,  g_w2p8);
    float4* rpef;
    cudaGetSymbolAddress((void**)&rpef, g_rpef);
    __half *qkvr, *attn;
    cudaGetSymbolAddress((void**)&qkvr, g_qkv_relay);
    cudaGetSymbolAddress((void**)&attn, g_attnout);

    // 7 launches/call: [convert, marker, pre0, main0, post0(+pre1), main1, post1]
    // -> ncu abs launch idx 3 = main0
    {
        int tot = 2 * WP_BLK + 2 * W2P8_BLK + 2 * RPEF_BLK;
        convert_all_kernel<<<(tot + 255) / 256, 256>>>(
            qkv_w, proj_w, w1, w2, rpe, wpall, w2p8, rpef);
    }
    marker_kernel<<<1, 32>>>();

    pre_kernel<<<128, THREADS, PRE_SMEM>>>(
        rt, wpall + WP_QKV, ln1_g, ln1_b, qkv_b, qkvr);

    for (int blk = 0; blk < 2; blk++) {
        const uint4* wpb  = wpall + (size_t)blk * WP_BLK;
        const uint4* w2pb = w2p8  + (size_t)blk * W2P8_BLK;
        const float* rtin  = (blk == 0) ? rt : brt;
        const float* din   = (blk == 0) ? data : bd;
        float*       dout  = (blk == 0) ? bd : out_data;
        float*       rtout = (blk == 0) ? brt : out_rt;
        const int o1 = blk * NC, o3 = blk * 3 * NC, oh = blk * NHID;

        hot_block_kernel<<<NWIN, THREADS, SMEM_BYTES>>>(
            din, wpb, w2pb, rpef + (size_t)blk * RPEF_BLK,
            rpe + (size_t)blk * NH * SW * SW, qkvr, attn,
            cpe_w + blk * 3 * NC, cpe_b + o1, ln1_g + o1, ln1_b + o1,
            qkv_b + o3, proj_b + o1, ln2_g + o1, ln2_b + o1,
            b1 + oh, b2 + o1, gamma1 + o1, gamma2 + o1, dout);

        const uint4* wqkv_n = (blk == 0) ? (wpall + WP_BLK + WP_QKV) : nullptr;
        post_kernel<<<128, THREADS, POST_SMEM>>>(
            rtin, attn, wpb + WP_PROJ, wpb + WP_W1, wpb + WP_W2,
            proj_b + o1, ln2_g + o1, ln2_b + o1, b1 + oh, b2 + o1,
            gamma1 + o1, gamma2 + o1, rtout,
            wqkv_n, ln1_g + NC, ln1_b + NC, qkv_b + 3 * NC, qkvr);
    }
}

// round 16
// speedup vs baseline: 1.0559x; 1.0559x over previous
#include <cuda_runtime.h>
#include <cuda_fp16.h>
#include <cuda_fp8.h>
#include <math.h>

// ---------------- problem constants ----------------
#define NC    256
#define NH    8
#define ND    32
#define KW    32
#define SW    33
#define NWIN  8192
#define NTOK  (NWIN*KW)
#define NHID  1024
#define ATT_SCALE 0.17677669529663687f
#define THREADS 256
#define WSCALE 64.0f
#define INVWS  0.015625f

// ---------------- smem pitches ----------------
#define XP  258    // xs fp32 pitch (elements)
#define HP  264    // hs fp16 pitch (elements)
#define BP  776    // qkv fp16 pitch (elements; 33 rows, row0 = relay)
#define MP  520    // post-kernel mlp hidden fp16 pitch (elements)
#define HDB 1040   // main-kernel mlp hidden fp8 pitch (BYTES)

#define XS_BYTES   34080
#define HS_BYTES   (33*HP*2)             // 17424
#define BIG_BYTES  (33*BP*2)             // 51216
#define SMEM_BYTES (XS_BYTES + HS_BYTES + BIG_BYTES)   // 102720 -> 2 CTA/SM

#define PRE_SMEM   (64*HP*2)
#define POST_SMEM  (64*XP*4 + 64*HP*2 + 64*MP*2)

// ---------------- global scratch ----------------
__device__ float  g_buf_data[(size_t)NTOK * NC];
__device__ float  g_buf_rt[(size_t)NWIN * NC];
__device__ __half g_qkv_relay[(size_t)NWIN * 768];
__device__ __half g_attnout[(size_t)NWIN * NC];

// fp16 weight B-fragments, PAIR-kt layout [nt][kt/2][lane] (uint4 counts / block)
#define WP_QKV  0
#define WP_PROJ 24576
#define WP_W1   32768
#define WP_W2   65536
#define WP_BLK  98304
__device__ uint4 g_wperm[2 * WP_BLK];

// fp8 w2 B-fragments (k32), PAIR-kt layout (uint4 counts / block)
#define W2P8_BLK 16384
__device__ uint4 g_w2p8[2 * W2P8_BLK];

// rpe in mma-C-fragment layout: [blk][h][mt(2)][nt(5)][lane(32)] float4
#define RPEF_BLK 2560
__device__ float4 g_rpef[2 * RPEF_BLK];

// ---------------- helpers ----------------
__device__ __forceinline__ unsigned sm_u32(const void* p) {
    return (unsigned)__cvta_generic_to_shared(p);
}
__device__ __forceinline__ unsigned pack2h(float a, float b) {
    __half2 h = __floats2half2_rn(a, b);
    return *reinterpret_cast<unsigned*>(&h);
}
__device__ __forceinline__ unsigned char to_fp8(float x) {
    return (unsigned char)__nv_cvt_float_to_fp8(x, __NV_SATFINITE, __NV_E4M3);
}
__device__ __forceinline__ unsigned short to_fp8x2(float x, float y) {
    float2 f = make_float2(x, y);
    return (unsigned short)__nv_cvt_float2_to_fp8x2(f, __NV_SATFINITE, __NV_E4M3);
}
__device__ __forceinline__ float gelu_tanh(float x) {
    float t = 0.7978845608028654f * (x + 0.044715f * x * x * x);
    float th;
    asm("tanh.approx.f32 %0, %1;" : "=f"(th) : "f"(t));
    return 0.5f * x * (1.f + th);
}
__device__ __forceinline__ void ldmat4(unsigned a[4], unsigned addr) {
    asm volatile("ldmatrix.sync.aligned.m8n8.x4.shared.b16 {%0,%1,%2,%3}, [%4];"
                 : "=r"(a[0]), "=r"(a[1]), "=r"(a[2]), "=r"(a[3]) : "r"(addr));
}
__device__ __forceinline__ void ldmat2(unsigned& b0, unsigned& b1, unsigned addr) {
    asm volatile("ldmatrix.sync.aligned.m8n8.x2.shared.b16 {%0,%1}, [%2];"
                 : "=r"(b0), "=r"(b1) : "r"(addr));
}
__device__ __forceinline__ void ldmat2t(unsigned& b0, unsigned& b1, unsigned addr) {
    asm volatile("ldmatrix.sync.aligned.m8n8.x2.trans.shared.b16 {%0,%1}, [%2];"
                 : "=r"(b0), "=r"(b1) : "r"(addr));
}
__device__ __forceinline__ void mma_f16(float c[4], const unsigned a[4], const uint2 b) {
    asm volatile("mma.sync.aligned.m16n8k16.row.col.f32.f16.f16.f32 "
                 "{%0,%1,%2,%3},{%4,%5,%6,%7},{%8,%9},{%0,%1,%2,%3};"
                 : "+f"(c[0]), "+f"(c[1]), "+f"(c[2]), "+f"(c[3])
                 : "r"(a[0]), "r"(a[1]), "r"(a[2]), "r"(a[3]), "r"(b.x), "r"(b.y));
}
__device__ __forceinline__ void mma_fp8(float c[4], const unsigned a[4], const uint2 b) {
    asm volatile("mma.sync.aligned.m16n8k32.row.col.f32.e4m3.e4m3.f32 "
                 "{%0,%1,%2,%3},{%4,%5,%6,%7},{%8,%9},{%0,%1,%2,%3};"
                 : "+f"(c[0]), "+f"(c[1]), "+f"(c[2]), "+f"(c[3])
                 : "r"(a[0]), "r"(a[1]), "r"(a[2]), "r"(a[3]), "r"(b.x), "r"(b.y));
}

// ---------------- fused conversion kernel ----------------
__global__ void convert_all_kernel(const float* __restrict__ qkv_w,
                                   const float* __restrict__ proj_w,
                                   const float* __restrict__ w1,
                                   const float* __restrict__ w2,
                                   const float* __restrict__ rpe,
                                   uint4* __restrict__ out16,
                                   uint4* __restrict__ out8,
                                   float4* __restrict__ rpef) {
    const int N16 = 2 * WP_BLK, N8 = 2 * W2P8_BLK, NRF = 2 * RPEF_BLK;
    int idx = blockIdx.x * blockDim.x + threadIdx.x;
    if (idx < N16) {
        const int blk = idx / WP_BLK;
        int r = idx - blk * WP_BLK;
        const float* W; int K, N; int local;
        if (r < WP_PROJ)      { W = qkv_w  + (size_t)blk * 256 * 768;  K = 256;  N = 768;  local = r; }
        else if (r < WP_W1)   { W = proj_w + (size_t)blk * 256 * 256;  K = 256;  N = 256;  local = r - WP_PROJ; }
        else if (r < WP_W2)   { W = w1     + (size_t)blk * 256 * 1024; K = 256;  N = 1024; local = r - WP_W1; }
        else                  { W = w2     + (size_t)blk * 1024 * 256; K = 1024; N = 256;  local = r - WP_W2; }
        const int lane = local & 31;
        const int t    = local >> 5;
        const int KT2  = K / 32;
        const int ktp  = t % KT2, nt = t / KT2;
        const int n    = nt * 8 + (lane >> 2);
        const int kA   = (2 * ktp) * 16 + (lane & 3) * 2;
        const int kB   = kA + 16;
        uint4 v;
        v.x = pack2h(W[(size_t)kA * N + n],       W[(size_t)(kA + 1) * N + n]);
        v.y = pack2h(W[(size_t)(kA + 8) * N + n], W[(size_t)(kA + 9) * N + n]);
        v.z = pack2h(W[(size_t)kB * N + n],       W[(size_t)(kB + 1) * N + n]);
        v.w = pack2h(W[(size_t)(kB + 8) * N + n], W[(size_t)(kB + 9) * N + n]);
        out16[idx] = v;
    } else if (idx < N16 + N8) {
        int j = idx - N16;
        const int blk = j / W2P8_BLK;
        int local = j - blk * W2P8_BLK;
        const float* W = w2 + (size_t)blk * 1024 * 256;
        const int lane = local & 31;
        const int t    = local >> 5;
        const int KT2  = 16;
        const int ktp  = t % KT2, nt = t / KT2;
        const int n    = nt * 8 + (lane >> 2);
        uint4 v; unsigned* vv = (unsigned*)&v;
        #pragma unroll
        for (int half = 0; half < 2; half++) {
            const int k0 = (2 * ktp + half) * 32 + (lane & 3) * 4;
            unsigned lo = 0, hi = 0;
            #pragma unroll
            for (int i = 0; i < 4; i++) {
                lo |= (unsigned)to_fp8(W[(size_t)(k0 + i)      * 256 + n] * WSCALE) << (8 * i);
                hi |= (unsigned)to_fp8(W[(size_t)(k0 + 16 + i) * 256 + n] * WSCALE) << (8 * i);
            }
            vv[2 * half] = lo; vv[2 * half + 1] = hi;
        }
        out8[j] = v;
    } else if (idx < N16 + N8 + NRF) {
        int j = idx - N16 - N8;
        const int blk  = j / RPEF_BLK;
        int rem  = j - blk * RPEF_BLK;            // [h][mt][nt][lane]
        const int h    = rem / 320;
        rem  = rem - h * 320;
        const int mt   = rem / 160;
        const int nt   = (rem % 160) / 32;
        const int lane = rem & 31;
        const int rr   = lane >> 2, cq = (lane & 3) * 2;
        const int q0   = mt * 16 + rr + 1, q1 = q0 + 8;
        const int k0   = nt * 8 + cq,      k1 = k0 + 1;
        const float* rh = rpe + ((size_t)blk * NH + h) * SW * SW;
        float4 v;
        v.x = (k0 <= 32) ? rh[q0 * SW + k0] : 0.f;
        v.y = (k1 <= 32) ? rh[q0 * SW + k1] : 0.f;
        v.z = (k0 <= 32) ? rh[q1 * SW + k0] : 0.f;
        v.w = (k1 <= 32) ? rh[q1 * SW + k1] : 0.f;
        rpef[j] = v;
    }
}

// one marker so ncu's profiled launch (abs idx 3) = main kernel block 0
__global__ void marker_kernel() {}

// ---------------- fp16 k-outer GEMM, pair-kt uint4 B loads ----------------
template<int MODE, int KSTEPS, int NT, int MT>
__device__ __forceinline__ void do_gemm(
    const __half* __restrict__ Ash, int apitch,
    const uint4* __restrict__ wmat, int KT2tot, int nt0, int ktp0,
    const float* __restrict__ bias, const float* __restrict__ gvec,
    __half* __restrict__ outh, float* __restrict__ outf,
    int opitch, int ocol0)
{
    const int lane = threadIdx.x & 31;
    float acc[MT][NT][4];
    #pragma unroll
    for (int mt = 0; mt < MT; mt++)
        #pragma unroll
        for (int j = 0; j < NT; j++)
            #pragma unroll
            for (int e = 0; e < 4; e++) acc[mt][j][e] = 0.f;

    unsigned abase[MT];
    #pragma unroll
    for (int mt = 0; mt < MT; mt++) {
        int row = mt * 16 + (lane & 15);
        abase[mt] = sm_u32(Ash + row * apitch + ((lane >> 4) << 3));
    }
    const uint4* wb = wmat + ((size_t)nt0 * KT2tot + ktp0) * 32 + lane;

    #pragma unroll 2
    for (int ktp = 0; ktp < KSTEPS / 2; ktp++) {
        uint4 bb[NT];
        #pragma unroll
        for (int j = 0; j < NT; j++) bb[j] = __ldg(wb + ((size_t)j * KT2tot + ktp) * 32);
        unsigned a[MT][4];
        #pragma unroll
        for (int mt = 0; mt < MT; mt++) ldmat4(a[mt], abase[mt] + (unsigned)(ktp * 64));
        #pragma unroll
        for (int mt = 0; mt < MT; mt++)
            #pragma unroll
            for (int j = 0; j < NT; j++) mma_f16(acc[mt][j], a[mt], make_uint2(bb[j].x, bb[j].y));
        #pragma unroll
        for (int mt = 0; mt < MT; mt++) ldmat4(a[mt], abase[mt] + (unsigned)(ktp * 64 + 32));
        #pragma unroll
        for (int mt = 0; mt < MT; mt++)
            #pragma unroll
            for (int j = 0; j < NT; j++) mma_f16(acc[mt][j], a[mt], make_uint2(bb[j].z, bb[j].w));
    }

    const int cq = (lane & 3) * 2;
    const int rr = lane >> 2;
    #pragma unroll
    for (int j = 0; j < NT; j++) {
        const int mcol = (nt0 + j) * 8 + cq;
        const int ocol = ocol0 + j * 8 + cq;
        float b0s = 0.f, b1s = 0.f;
        if (bias) { b0s = bias[mcol]; b1s = bias[mcol + 1]; }
        float g0 = 0.f, g1 = 0.f;
        if (MODE == 2) { g0 = gvec[ocol]; g1 = gvec[ocol + 1]; }
        #pragma unroll
        for (int mt = 0; mt < MT; mt++) {
            const int r0 = mt * 16 + rr, r1 = r0 + 8;
            const float* a4 = acc[mt][j];
            const float v00 = a4[0] + b0s, v01 = a4[1] + b1s;
            const float v10 = a4[2] + b0s, v11 = a4[3] + b1s;
            if (MODE == 0) {
                *(unsigned*)(outh + r0 * opitch + ocol) = pack2h(v00, v01);
                *(unsigned*)(outh + r1 * opitch + ocol) = pack2h(v10, v11);
            } else if (MODE == 1) {
                *(unsigned*)(outh + r0 * opitch + ocol) = pack2h(gelu_tanh(v00), gelu_tanh(v01));
                *(unsigned*)(outh + r1 * opitch + ocol) = pack2h(gelu_tanh(v10), gelu_tanh(v11));
            } else {
                float* p0 = outf + r0 * opitch + ocol;
                p0[0] += g0 * v00; p0[1] += g1 * v01;
                float* p1 = outf + r1 * opitch + ocol;
                p1[0] += g0 * v10; p1[1] += g1 * v11;
            }
        }
    }
}

// ---------------- w1 GEMM: fp16 mma, gelu -> fp8 packed (MT=2) ----------------
template<int KSTEPS, int NT>
__device__ __forceinline__ void do_gemm_gelu8(
    const __half* __restrict__ Ash, int apitch,
    const uint4* __restrict__ wmat, int KT2tot, int nt0,
    const float* __restrict__ bias,
    unsigned char* __restrict__ out8, int opitchB, int ocol0)
{
    const int lane = threadIdx.x & 31;
    float acc[2][NT][4];
    #pragma unroll
    for (int mt = 0; mt < 2; mt++)
        #pragma unroll
        for (int j = 0; j < NT; j++)
            #pragma unroll
            for (int e = 0; e < 4; e++) acc[mt][j][e] = 0.f;

    unsigned abase[2];
    #pragma unroll
    for (int mt = 0; mt < 2; mt++) {
        int row = mt * 16 + (lane & 15);
        abase[mt] = sm_u32(Ash + row * apitch + ((lane >> 4) << 3));
    }
    const uint4* wb = wmat + (size_t)nt0 * KT2tot * 32 + lane;

    #pragma unroll 2
    for (int ktp = 0; ktp < KSTEPS / 2; ktp++) {
        uint4 bb[NT];
        #pragma unroll
        for (int j = 0; j < NT; j++) bb[j] = __ldg(wb + ((size_t)j * KT2tot + ktp) * 32);
        unsigned a[2][4];
        #pragma unroll
        for (int mt = 0; mt < 2; mt++) ldmat4(a[mt], abase[mt] + (unsigned)(ktp * 64));
        #pragma unroll
        for (int mt = 0; mt < 2; mt++)
            #pragma unroll
            for (int j = 0; j < NT; j++) mma_f16(acc[mt][j], a[mt], make_uint2(bb[j].x, bb[j].y));
        #pragma unroll
        for (int mt = 0; mt < 2; mt++) ldmat4(a[mt], abase[mt] + (unsigned)(ktp * 64 + 32));
        #pragma unroll
        for (int mt = 0; mt < 2; mt++)
            #pragma unroll
            for (int j = 0; j < NT; j++) mma_f16(acc[mt][j], a[mt], make_uint2(bb[j].z, bb[j].w));
    }

    const int cq = (lane & 3) * 2;
    const int rr = lane >> 2;
    #pragma unroll
    for (int j = 0; j < NT; j++) {
        const int mcol = (nt0 + j) * 8 + cq;
        const int ocol = ocol0 + j * 8 + cq;
        const float b0s = bias[mcol], b1s = bias[mcol + 1];
        #pragma unroll
        for (int mt = 0; mt < 2; mt++) {
            const int r0 = mt * 16 + rr, r1 = r0 + 8;
            const float* a4 = acc[mt][j];
            *(unsigned short*)(out8 + r0 * opitchB + ocol) =
                to_fp8x2(gelu_tanh(a4[0] + b0s), gelu_tanh(a4[1] + b1s));
            *(unsigned short*)(out8 + r1 * opitchB + ocol) =
                to_fp8x2(gelu_tanh(a4[2] + b0s), gelu_tanh(a4[3] + b1s));
        }
    }
}

// ---------------- w2 GEMM: fp8 x fp8 (k32 paired); final epilogue:
// out_gmem[r][ocol] = xs_smem[r][ocol] + gamma * (acc/64 + bias)   (pure store)
template<int KSTEPS>
__device__ __forceinline__ void do_gemm8_final(
    const unsigned char* __restrict__ Ash, int apitchB,
    const uint4* __restrict__ wmat, int KT2tot, int nt0,
    const float* __restrict__ bias, const float* __restrict__ gvec,
    const float* __restrict__ xsin,   // smem, pitch XP, row 0 = data row 0
    float* __restrict__ outg,         // gmem, pitch NC
    int ocol0)
{
    const int lane = threadIdx.x & 31;
    float acc[2][4][4];
    #pragma unroll
    for (int mt = 0; mt < 2; mt++)
        #pragma unroll
        for (int j = 0; j < 4; j++)
            #pragma unroll
            for (int e = 0; e < 4; e++) acc[mt][j][e] = 0.f;

    unsigned abase[2];
    #pragma unroll
    for (int mt = 0; mt < 2; mt++) {
        int row = mt * 16 + (lane & 15);
        abase[mt] = sm_u32(Ash + row * apitchB + ((lane >> 4) << 4));
    }
    const uint4* wb = wmat + (size_t)nt0 * KT2tot * 32 + lane;

    #pragma unroll 2
    for (int ktp = 0; ktp < KSTEPS / 2; ktp++) {
        uint4 bb[4];
        #pragma unroll
        for (int j = 0; j < 4; j++) bb[j] = __ldg(wb + ((size_t)j * KT2tot + ktp) * 32);
        unsigned a[2][4];
        #pragma unroll
        for (int mt = 0; mt < 2; mt++) ldmat4(a[mt], abase[mt] + (unsigned)(ktp * 64));
        #pragma unroll
        for (int mt = 0; mt < 2; mt++)
            #pragma unroll
            for (int j = 0; j < 4; j++) mma_fp8(acc[mt][j], a[mt], make_uint2(bb[j].x, bb[j].y));
        #pragma unroll
        for (int mt = 0; mt < 2; mt++) ldmat4(a[mt], abase[mt] + (unsigned)(ktp * 64 + 32));
        #pragma unroll
        for (int mt = 0; mt < 2; mt++)
            #pragma unroll
            for (int j = 0; j < 4; j++) mma_fp8(acc[mt][j], a[mt], make_uint2(bb[j].z, bb[j].w));
    }

    const int cq = (lane & 3) * 2;
    const int rr = lane >> 2;
    #pragma unroll
    for (int j = 0; j < 4; j++) {
        const int mcol = (nt0 + j) * 8 + cq;
        const int ocol = ocol0 + j * 8 + cq;
        const float b0s = bias[mcol], b1s = bias[mcol + 1];
        const float g0 = gvec[ocol], g1 = gvec[ocol + 1];
        #pragma unroll
        for (int mt = 0; mt < 2; mt++) {
            const int r0 = mt * 16 + rr, r1 = r0 + 8;
            const float* a4 = acc[mt][j];
            const float* x0 = xsin + r0 * XP + ocol;
            const float* x1 = xsin + r1 * XP + ocol;
            float2 o0, o1;
            o0.x = x0[0] + g0 * fmaf(a4[0], INVWS, b0s);
            o0.y = x0[1] + g1 * fmaf(a4[1], INVWS, b1s);
            o1.x = x1[0] + g0 * fmaf(a4[2], INVWS, b0s);
            o1.y = x1[1] + g1 * fmaf(a4[3], INVWS, b1s);
            *(float2*)(outg + r0 * NC + ocol) = o0;
            *(float2*)(outg + r1 * NC + ocol) = o1;
        }
    }
}

// ---------------- w2 GEMM for post kernel (smem RMW epilogue) ----------------
template<int KSTEPS>
__device__ __forceinline__ void do_gemm8_post(
    const __half* __restrict__ Ash, int apitch,   // unused variant kept simple
    const uint4* __restrict__ wmat, int KT2tot, int nt0,
    const float* __restrict__ bias, const float* __restrict__ gvec,
    float* __restrict__ outf, int opitch, int ocol0)
{
    (void)Ash; (void)apitch; (void)wmat; (void)KT2tot; (void)nt0;
    (void)bias; (void)gvec; (void)outf; (void)opitch; (void)ocol0;
}

// hfma2 dot: 16 half2 pairs -> fp32 scalar (relay path)
__device__ __forceinline__ float dot32_h2(const __half2* a, const __half2* b) {
    __half2 acc0 = __hmul2(a[0], b[0]);
    __half2 acc1 = __hmul2(a[1], b[1]);
    #pragma unroll
    for (int i = 2; i < 16; i += 2) {
        acc0 = __hfma2(a[i],     b[i],     acc0);
        acc1 = __hfma2(a[i + 1], b[i + 1], acc1);
    }
    __half2 acc = __hadd2(acc0, acc1);
    return __half2float(__low2half(acc)) + __half2float(__high2half(acc));
}

// LN rows helper for 64-row pre/post tiles
__device__ __forceinline__ void ln_rows64(
    const float* __restrict__ X, int xpitch, __half* __restrict__ Out,
    const float* __restrict__ g, const float* __restrict__ b)
{
    const int wq = threadIdx.x >> 5, lane = threadIdx.x & 31;
    for (int row = wq; row < 64; row += 8) {
        const float* rp = X + row * xpitch;
        float sum = 0.f, sum2 = 0.f;
        #pragma unroll
        for (int c = lane; c < NC; c += 32) { float v = rp[c]; sum += v; sum2 += v * v; }
        #pragma unroll
        for (int o = 16; o; o >>= 1) {
            sum  += __shfl_xor_sync(0xffffffffu, sum, o);
            sum2 += __shfl_xor_sync(0xffffffffu, sum2, o);
        }
        const float m    = sum * (1.f / NC);
        const float var  = fmaxf(sum2 * (1.f / NC) - m * m, 0.f);
        const float rstd = rsqrtf(var + 1e-5f);
        #pragma unroll
        for (int c = lane; c < NC; c += 32)
            Out[row * HP + c] = __float2half_rn((rp[c] - m) * rstd * g[c] + b[c]);
    }
}

// ---------------- pre kernel: relay LN1 + qkv (block 0 only) ----------------
__global__ void __launch_bounds__(THREADS, 1)
pre_kernel(const float* __restrict__ rt_in, const uint4* __restrict__ wqkv,
           const float* __restrict__ ln1_g, const float* __restrict__ ln1_b,
           const float* __restrict__ qkv_b, __half* __restrict__ qkv_relay)
{
    extern __shared__ char sm8[];
    __half* hs = (__half*)sm8;
    const int tid = threadIdx.x, wq = tid >> 5, lane = tid & 31;
    const int r0 = blockIdx.x * 64;

    for (int row = wq; row < 64; row += 8) {
        const float* rp = rt_in + (size_t)(r0 + row) * NC;
        float v[8], sum = 0.f, sum2 = 0.f;
        #pragma unroll
        for (int i = 0; i < 8; i++) {
            v[i] = rp[lane + 32 * i];
            sum += v[i]; sum2 += v[i] * v[i];
        }
        #pragma unroll
        for (int o = 16; o; o >>= 1) {
            sum  += __shfl_xor_sync(0xffffffffu, sum, o);
            sum2 += __shfl_xor_sync(0xffffffffu, sum2, o);
        }
        const float m    = sum * (1.f / NC);
        const float var  = fmaxf(sum2 * (1.f / NC) - m * m, 0.f);
        const float rstd = rsqrtf(var + 1e-5f);
        #pragma unroll
        for (int i = 0; i < 8; i++) {
            const int c = lane + 32 * i;
            hs[row * HP + c] = __float2half_rn((v[i] - m) * rstd * ln1_g[c] + ln1_b[c]);
        }
    }
    __syncthreads();

    __half* outg = qkv_relay + (size_t)r0 * 768;
    #pragma unroll 1
    for (int p = 0; p < 2; p++) {
        const int nt = wq * 12 + p * 6;
        do_gemm<0, 16, 6, 4>(hs, HP, wqkv, 8, nt, 0, qkv_b, nullptr,
                             outg, nullptr, 768, nt * 8);
    }
}

// ---------------- post kernel: relay proj+LN2+MLP (+ fused next-block pre) ----------------
__global__ void __launch_bounds__(THREADS, 1)
post_kernel(const float* __restrict__ rt_in, const __half* __restrict__ attnout,
            const uint4* __restrict__ wproj, const uint4* __restrict__ w1p,
            const uint4* __restrict__ w2p,
            const float* __restrict__ proj_b,
            const float* __restrict__ ln2_g, const float* __restrict__ ln2_b,
            const float* __restrict__ b1,   const float* __restrict__ b2,
            const float* __restrict__ gamma1, const float* __restrict__ gamma2,
            float* __restrict__ out_rt,
            const uint4* __restrict__ wqkv_n,
            const float* __restrict__ ln1_g_n, const float* __restrict__ ln1_b_n,
            const float* __restrict__ qkv_b_n, __half* __restrict__ qkv_relay_n)
{
    extern __shared__ char sm8[];
    float*  xs  = (float*)sm8;
    __half* hs  = (__half*)(sm8 + 64 * XP * 4);
    __half* hid = (__half*)(sm8 + 64 * XP * 4 + 64 * HP * 2);
    const int tid = threadIdx.x, wq = tid >> 5, lane = tid & 31;
    const int r0 = blockIdx.x * 64;

    for (int idx = tid; idx < 64 * NC; idx += THREADS) {
        const int row = idx >> 8, c = idx & 255;
        xs[row * XP + c] = rt_in[(size_t)(r0 + row) * NC + c];
        hs[row * HP + c] = attnout[(size_t)(r0 + row) * NC + c];
    }
    __syncthreads();

    do_gemm<2, 16, 4, 4>(hs, HP, wproj, 8, wq * 4, 0, proj_b, gamma1,
                         nullptr, xs, XP, wq * 32);
    __syncthreads();

    ln_rows64(xs, XP, hs, ln2_g, ln2_b);
    __syncthreads();

    #pragma unroll 1
    for (int c = 0; c < 2; c++) {
        #pragma unroll 1
        for (int p = 0; p < 2; p++) {
            const int nt = c * 64 + wq * 8 + p * 4;
            do_gemm<1, 16, 4, 4>(hs, HP, w1p, 8, nt, 0, b1, nullptr,
                                 hid, nullptr, MP, nt * 8 - c * 512);
        }
        __syncthreads();
        do_gemm<2, 32, 4, 4>(hid, MP, w2p, 32, wq * 4, c * 16,
                             (c == 0) ? b2 : nullptr, gamma2, nullptr, xs, XP, wq * 32);
        __syncthreads();
    }

    for (int idx = tid; idx < 64 * NC; idx += THREADS) {
        const int row = idx >> 8, c = idx & 255;
        out_rt[(size_t)(r0 + row) * NC + c] = xs[row * XP + c];
    }

    // ---- fused pre of next block: LN1(new rt) + qkv ----
    if (wqkv_n) {
        __syncthreads();
        ln_rows64(xs, XP, hs, ln1_g_n, ln1_b_n);
        __syncthreads();
        __half* outg = qkv_relay_n + (size_t)r0 * 768;
        #pragma unroll 1
        for (int p = 0; p < 2; p++) {
            const int nt = wq * 12 + p * 6;
            do_gemm<0, 16, 6, 4>(hs, HP, wqkv_n, 8, nt, 0, qkv_b_n, nullptr,
                                 outg, nullptr, 768, nt * 8);
        }
    }
}

// ---------------- main fused window kernel (32 data rows, xs in smem) ----------------
__global__ void __launch_bounds__(THREADS, 2)
hot_block_kernel(
    const float* __restrict__ in_data,
    const uint4* __restrict__ wp,     const uint4* __restrict__ w2p8,
    const float4* __restrict__ rpef,  const float* __restrict__ rpe0,
    const __half* __restrict__ qkv_relay, __half* __restrict__ attnout,
    const float* __restrict__ cpe_w,  const float* __restrict__ cpe_b,
    const float* __restrict__ ln1_g,  const float* __restrict__ ln1_b,
    const float* __restrict__ qkv_b,
    const float* __restrict__ proj_b,
    const float* __restrict__ ln2_g,  const float* __restrict__ ln2_b,
    const float* __restrict__ b1,     const float* __restrict__ b2,
    const float* __restrict__ gamma1, const float* __restrict__ gamma2,
    float* __restrict__ out_data)
{
    extern __shared__ char sm8[];
    float*  xs  = (float*)sm8;                          // [33][258] (row0 unused)
    __half* hs  = (__half*)(sm8 + XS_BYTES);            // [33][264] (row0 unused)
    __half* big = (__half*)(sm8 + XS_BYTES + HS_BYTES); // [33][776] qkv
    unsigned char* hid8 = (unsigned char*)big;          // fp8 hidden [32][1040B] overlays

    const int tid  = threadIdx.x;
    const int wq   = tid >> 5;
    const int lane = tid & 31;
    const int w    = blockIdx.x;

    const uint4* wqkv  = wp + WP_QKV;
    const uint4* wproj = wp + WP_PROJ;
    const uint4* w1p   = wp + WP_W1;

    // ---- Phase A: cpe + LN1 fused (vectorized gmem loads) + relay qkv load ----
    {
        const int c0 = lane * 8;
        for (int s = 1 + wq; s < SW; s += 8) {
            const long r = (long)w * KW + (s - 1);
            const float* row0 = in_data + r * NC + c0;
            float4 xa = *(const float4*)row0;
            float4 xb = *(const float4*)(row0 + 4);
            float4 ma, mb, pa, pb;
            if (r > 0) { ma = *(const float4*)(row0 - NC); mb = *(const float4*)(row0 - NC + 4); }
            else       { ma = make_float4(0,0,0,0); mb = ma; }
            if (r < NTOK - 1) { pa = *(const float4*)(row0 + NC); pb = *(const float4*)(row0 + NC + 4); }
            else       { pa = make_float4(0,0,0,0); pb = pa; }
            const float4 c0a = *(const float4*)(cpe_w + c0),        c0b = *(const float4*)(cpe_w + c0 + 4);
            const float4 c1a = *(const float4*)(cpe_w + NC + c0),   c1b = *(const float4*)(cpe_w + NC + c0 + 4);
            const float4 c2a = *(const float4*)(cpe_w + 2*NC + c0), c2b = *(const float4*)(cpe_w + 2*NC + c0 + 4);
            const float4 cba = *(const float4*)(cpe_b + c0),        cbb = *(const float4*)(cpe_b + c0 + 4);
            float v[8];
            v[0] = xa.x + ma.x*c0a.x + xa.x*c1a.x + pa.x*c2a.x + cba.x;
            v[1] = xa.y + ma.y*c0a.y + xa.y*c1a.y + pa.y*c2a.y + cba.y;
            v[2] = xa.z + ma.z*c0a.z + xa.z*c1a.z + pa.z*c2a.z + cba.z;
            v[3] = xa.w + ma.w*c0a.w + xa.w*c1a.w + pa.w*c2a.w + cba.w;
            v[4] = xb.x + mb.x*c0b.x + xb.x*c1b.x + pb.x*c2b.x + cbb.x;
            v[5] = xb.y + mb.y*c0b.y + xb.y*c1b.y + pb.y*c2b.y + cbb.y;
            v[6] = xb.z + mb.z*c0b.z + xb.z*c1b.z + pb.z*c2b.z + cbb.z;
            v[7] = xb.w + mb.w*c0b.w + xb.w*c1b.w + pb.w*c2b.w + cbb.w;
            float sum = 0.f, sum2 = 0.f;
            #pragma unroll
            for (int i = 0; i < 8; i++) { sum += v[i]; sum2 += v[i]*v[i]; }
            #pragma unroll
            for (int o = 16; o; o >>= 1) {
                sum  += __shfl_xor_sync(0xffffffffu, sum, o);
                sum2 += __shfl_xor_sync(0xffffffffu, sum2, o);
            }
            const float m    = sum * (1.f / NC);
            const float var  = fmaxf(sum2 * (1.f / NC) - m * m, 0.f);
            const float rstd = rsqrtf(var + 1e-5f);
            float* xw = xs + s * XP + c0;
            *(float2*)(xw)     = make_float2(v[0], v[1]);
            *(float2*)(xw + 2) = make_float2(v[2], v[3]);
            *(float2*)(xw + 4) = make_float2(v[4], v[5]);
            *(float2*)(xw + 6) = make_float2(v[6], v[7]);
            const float4 ga = *(const float4*)(ln1_g + c0), gb = *(const float4*)(ln1_g + c0 + 4);
            const float4 ba = *(const float4*)(ln1_b + c0), bb4 = *(const float4*)(ln1_b + c0 + 4);
            unsigned hh[4];
            hh[0] = pack2h((v[0]-m)*rstd*ga.x + ba.x,  (v[1]-m)*rstd*ga.y + ba.y);
            hh[1] = pack2h((v[2]-m)*rstd*ga.z + ba.z,  (v[3]-m)*rstd*ga.w + ba.w);
            hh[2] = pack2h((v[4]-m)*rstd*gb.x + bb4.x, (v[5]-m)*rstd*gb.y + bb4.y);
            hh[3] = pack2h((v[6]-m)*rstd*gb.z + bb4.z, (v[7]-m)*rstd*gb.w + bb4.w);
            *(uint4*)(hs + s * HP + c0) = *(uint4*)hh;
        }
    }
    {   // relay qkv -> big row 0
        const unsigned* src = (const unsigned*)(qkv_relay + (size_t)w * 768);
        unsigned* dst = (unsigned*)big;
        for (int idx = tid; idx < 384; idx += THREADS) dst[idx] = src[idx];
    }
    __syncthreads();

    // ---- Phase C: qkv (data rows) -> big rows 1..32 ----
    #pragma unroll 1
    for (int p = 0; p < 2; p++) {
        const int nt = wq * 12 + p * 6;
        do_gemm<0, 16, 6, 2>(hs + HP, HP, wqkv, 8, nt, 0, qkv_b, nullptr,
                             big + BP, nullptr, BP, nt * 8);
    }
    __syncthreads();

    // ---- Phase D: attention via tensor cores (warp = head) ----
    {
        const int h  = wq;
        const int rr = lane >> 2, cq = (lane & 3) * 2;
        const int L  = lane & 15;

        uint2 bk[5][2];
        #pragma unroll
        for (int nt = 0; nt < 5; nt++) {
            int key = nt * 8 + (L & 7); if (key > 32) key = 32;
            #pragma unroll
            for (int kt = 0; kt < 2; kt++)
                ldmat2(bk[nt][kt].x, bk[nt][kt].y,
                       sm_u32(big + key * BP + 256 + h * ND + kt * 16 + ((L >> 3) << 3)));
        }

        float accS[2][5][4];
        #pragma unroll
        for (int mt = 0; mt < 2; mt++)
            #pragma unroll
            for (int nt = 0; nt < 5; nt++)
                #pragma unroll
                for (int e = 0; e < 4; e++) accS[mt][nt][e] = 0.f;
        #pragma unroll
        for (int mt = 0; mt < 2; mt++) {
            #pragma unroll
            for (int kt = 0; kt < 2; kt++) {
                unsigned aq[4];
                ldmat4(aq, sm_u32(big + (1 + mt * 16 + L) * BP + h * ND
                                  + ((lane >> 4) << 3) + kt * 16));
                #pragma unroll
                for (int nt = 0; nt < 5; nt++) mma_f16(accS[mt][nt], aq, bk[nt][kt]);
            }
        }

        const float4* rpef_h = rpef + h * 320;
        float sum0[2], sum1[2];
        unsigned ap[2][3][4];
        #pragma unroll
        for (int mt = 0; mt < 2; mt++) {
            float p[5][4];
            float s0 = 0.f, s1 = 0.f;
            #pragma unroll
            for (int nt = 0; nt < 5; nt++) {
                const float4 rv = rpef_h[(mt * 5 + nt) * 32 + lane];
                float e0 = __expf(fmaf(accS[mt][nt][0], ATT_SCALE, rv.x));
                float e1 = __expf(fmaf(accS[mt][nt][1], ATT_SCALE, rv.y));
                float e2 = __expf(fmaf(accS[mt][nt][2], ATT_SCALE, rv.z));
                float e3 = __expf(fmaf(accS[mt][nt][3], ATT_SCALE, rv.w));
                if (nt == 4) {
                    const bool vld = (cq == 0);
                    e0 = vld ? e0 : 0.f; e2 = vld ? e2 : 0.f;
                    e1 = 0.f; e3 = 0.f;
                }
                p[nt][0] = e0; p[nt][1] = e1; p[nt][2] = e2; p[nt][3] = e3;
                s0 += e0 + e1; s1 += e2 + e3;
            }
            s0 += __shfl_xor_sync(0xffffffffu, s0, 1);
            s0 += __shfl_xor_sync(0xffffffffu, s0, 2);
            s1 += __shfl_xor_sync(0xffffffffu, s1, 1);
            s1 += __shfl_xor_sync(0xffffffffu, s1, 2);
            sum0[mt] = s0; sum1[mt] = s1;
            #pragma unroll
            for (int s = 0; s < 3; s++) {
                const int n0 = 2 * s, n1 = 2 * s + 1;
                ap[mt][s][0] = pack2h(p[n0][0], p[n0][1]);
                ap[mt][s][1] = pack2h(p[n0][2], p[n0][3]);
                ap[mt][s][2] = (n1 < 5) ? pack2h(p[n1][0], p[n1][1]) : 0u;
                ap[mt][s][3] = (n1 < 5) ? pack2h(p[n1][2], p[n1][3]) : 0u;
            }
        }

        float accO[2][4][4];
        #pragma unroll
        for (int mt = 0; mt < 2; mt++)
            #pragma unroll
            for (int nt = 0; nt < 4; nt++)
                #pragma unroll
                for (int e = 0; e < 4; e++) accO[mt][nt][e] = 0.f;
        #pragma unroll
        for (int kt = 0; kt < 3; kt++) {
            int key = kt * 16 + L; if (key > 32) key = 32;
            uint2 bv[4];
            #pragma unroll
            for (int nt = 0; nt < 4; nt++)
                ldmat2t(bv[nt].x, bv[nt].y,
                        sm_u32(big + key * BP + 512 + h * ND + nt * 8));
            #pragma unroll
            for (int mt = 0; mt < 2; mt++)
                #pragma unroll
                for (int nt = 0; nt < 4; nt++) mma_f16(accO[mt][nt], ap[mt][kt], bv[nt]);
        }

        #pragma unroll
        for (int mt = 0; mt < 2; mt++) {
            const float i0 = 1.f / sum0[mt], i1 = 1.f / sum1[mt];
            #pragma unroll
            for (int nt = 0; nt < 4; nt++) {
                const int d = nt * 8 + cq;
                *(unsigned*)(hs + (1 + mt * 16 + rr) * HP + h * ND + d) =
                    pack2h(accO[mt][nt][0] * i0, accO[mt][nt][1] * i0);
                *(unsigned*)(hs + (9 + mt * 16 + rr) * HP + h * ND + d) =
                    pack2h(accO[mt][nt][2] * i1, accO[mt][nt][3] * i1);
            }
        }

        // relay query (ref q = 0): scalar path
        const float* rp0 = rpe0 + h * SW * SW;
        __half2 q0h[16], kh[16];
        {
            const uint4* qp = (const uint4*)(big + h * ND);
            #pragma unroll
            for (int i = 0; i < 4; i++) ((uint4*)q0h)[i] = qp[i];
        }
        {
            const uint4* kp = (const uint4*)(big + lane * BP + 256 + h * ND);
            #pragma unroll
            for (int i = 0; i < 4; i++) ((uint4*)kh)[i] = kp[i];
        }
        float e = __expf(fmaf(dot32_h2(q0h, kh), ATT_SCALE, rp0[lane]));
        {
            const uint4* kp = (const uint4*)(big + 32 * BP + 256 + h * ND);
            #pragma unroll
            for (int i = 0; i < 4; i++) ((uint4*)kh)[i] = kp[i];
        }
        const float e32 = __expf(fmaf(dot32_h2(q0h, kh), ATT_SCALE, rp0[32]));
        float d = e;
        #pragma unroll
        for (int o = 16; o; o >>= 1) d += __shfl_xor_sync(0xffffffffu, d, o);
        d += e32;
        const float invd = 1.f / d;
        const float pr   = e * invd;
        float o = (e32 * invd) * __half2float(big[32 * BP + 512 + h * ND + lane]);
        #pragma unroll 4
        for (int k = 0; k < 32; k++) {
            const float pk = __shfl_sync(0xffffffffu, pr, k);
            o = fmaf(pk, __half2float(big[k * BP + 512 + h * ND + lane]), o);
        }
        attnout[(size_t)w * NC + h * ND + lane] = __float2half_rn(o);
    }
    __syncthreads();

    // ---- Phase E: xs += gamma1 * (o @ proj_w + proj_b)  (smem RMW) ----
    do_gemm<2, 16, 4, 2>(hs + HP, HP, wproj, 8, wq * 4, 0, proj_b, gamma1,
                         nullptr, xs + XP, XP, wq * 32);
    __syncthreads();

    // ---- Phase F: LN2 (vectorized smem reads) ----
    {
        const int c0 = lane * 8;
        for (int s = 1 + wq; s < SW; s += 8) {
            const float* rp = xs + s * XP + c0;
            const float2 v0 = *(const float2*)rp;
            const float2 v1 = *(const float2*)(rp + 2);
            const float2 v2 = *(const float2*)(rp + 4);
            const float2 v3 = *(const float2*)(rp + 6);
            float sum  = v0.x + v0.y + v1.x + v1.y + v2.x + v2.y + v3.x + v3.y;
            float sum2 = v0.x*v0.x + v0.y*v0.y + v1.x*v1.x + v1.y*v1.y
                       + v2.x*v2.x + v2.y*v2.y + v3.x*v3.x + v3.y*v3.y;
            #pragma unroll
            for (int o = 16; o; o >>= 1) {
                sum  += __shfl_xor_sync(0xffffffffu, sum, o);
                sum2 += __shfl_xor_sync(0xffffffffu, sum2, o);
            }
            const float m    = sum * (1.f / NC);
            const float var  = fmaxf(sum2 * (1.f / NC) - m * m, 0.f);
            const float rstd = rsqrtf(var + 1e-5f);
            const float4 ga = *(const float4*)(ln2_g + c0), gb = *(const float4*)(ln2_g + c0 + 4);
            const float4 ba = *(const float4*)(ln2_b + c0), bb4 = *(const float4*)(ln2_b + c0 + 4);
            unsigned hh[4];
            hh[0] = pack2h((v0.x-m)*rstd*ga.x + ba.x,  (v0.y-m)*rstd*ga.y + ba.y);
            hh[1] = pack2h((v1.x-m)*rstd*ga.z + ba.z,  (v1.y-m)*rstd*ga.w + ba.w);
            hh[2] = pack2h((v2.x-m)*rstd*gb.x + bb4.x, (v2.y-m)*rstd*gb.y + bb4.y);
            hh[3] = pack2h((v3.x-m)*rstd*gb.z + bb4.z, (v3.y-m)*rstd*gb.w + bb4.w);
            *(uint4*)(hs + s * HP + c0) = *(uint4*)hh;
        }
    }
    __syncthreads();

    // ---- Phase G: MLP single-pass, hidden fp8; w2 final epilogue -> out gmem ----
    #pragma unroll 1
    for (int p = 0; p < 2; p++) {
        const int nt = wq * 16 + p * 8;
        do_gemm_gelu8<16, 8>(hs + HP, HP, w1p, 8, nt, b1, hid8, HDB, nt * 8);
    }
    __syncthreads();
    do_gemm8_final<32>(hid8, HDB, w2p8, 16, wq * 4, b2, gamma2,
                       xs + XP, out_data + (size_t)w * KW * NC, wq * 32);
    // output written directly — no Phase H.
}

// ---------------- host launch ----------------
extern "C" void kernel_launch(void* const* d_in, const int* in_sizes, int n_in,
                              void* d_out, int out_size) {
    (void)in_sizes; (void)n_in; (void)out_size;
    const float* data   = (const float*)d_in[0];
    const float* rt     = (const float*)d_in[1];
    const float* cpe_w  = (const float*)d_in[2];
    const float* cpe_b  = (const float*)d_in[3];
    const float* ln1_g  = (const float*)d_in[4];
    const float* ln1_b  = (const float*)d_in[5];
    const float* qkv_w  = (const float*)d_in[6];
    const float* qkv_b  = (const float*)d_in[7];
    const float* rpe    = (const float*)d_in[8];
    const float* proj_w = (const float*)d_in[9];
    const float* proj_b = (const float*)d_in[10];
    const float* ln2_g  = (const float*)d_in[11];
    const float* ln2_b  = (const float*)d_in[12];
    const float* w1     = (const float*)d_in[13];
    const float* b1     = (const float*)d_in[14];
    const float* w2     = (const float*)d_in[15];
    const float* b2     = (const float*)d_in[16];
    const float* gamma1 = (const float*)d_in[17];
    const float* gamma2 = (const float*)d_in[18];

    float* out_data = (float*)d_out;
    float* out_rt   = out_data + (size_t)NTOK * NC;

    cudaFuncSetAttribute(hot_block_kernel,
                         cudaFuncAttributeMaxDynamicSharedMemorySize, SMEM_BYTES);
    cudaFuncSetAttribute(pre_kernel,
                         cudaFuncAttributeMaxDynamicSharedMemorySize, PRE_SMEM);
    cudaFuncSetAttribute(post_kernel,
                         cudaFuncAttributeMaxDynamicSharedMemorySize, POST_SMEM);

    float *bd, *brt;
    cudaGetSymbolAddress((void**)&bd,  g_buf_data);
    cudaGetSymbolAddress((void**)&brt, g_buf_rt);
    uint4 *wpall, *w2p8;
    cudaGetSymbolAddress((void**)&wpall, g_wperm);
    cudaGetSymbolAddress((void**)&w2p8,  g_w2p8);
    float4* rpef;
    cudaGetSymbolAddress((void**)&rpef, g_rpef);
    __half *qkvr, *attn;
    cudaGetSymbolAddress((void**)&qkvr, g_qkv_relay);
    cudaGetSymbolAddress((void**)&attn, g_attnout);

    // 7 launches/call: [convert, marker, pre0, main0, post0(+pre1), main1, post1]
    // -> ncu abs launch idx 3 = main0
    {
        int tot = 2 * WP_BLK + 2 * W2P8_BLK + 2 * RPEF_BLK;
        convert_all_kernel<<<(tot + 255) / 256, 256>>>(
            qkv_w, proj_w, w1, w2, rpe, wpall, w2p8, rpef);
    }
    marker_kernel<<<1, 32>>>();

    pre_kernel<<<128, THREADS, PRE_SMEM>>>(
        rt, wpall + WP_QKV, ln1_g, ln1_b, qkv_b, qkvr);

    for (int blk = 0; blk < 2; blk++) {
        const uint4* wpb  = wpall + (size_t)blk * WP_BLK;
        const uint4* w2pb = w2p8  + (size_t)blk * W2P8_BLK;
        const float* rtin  = (blk == 0) ? rt : brt;
        const float* din   = (blk == 0) ? data : bd;
        float*       dout  = (blk == 0) ? bd : out_data;
        float*       rtout = (blk == 0) ? brt : out_rt;
        const int o1 = blk * NC, o3 = blk * 3 * NC, oh = blk * NHID;

        hot_block_kernel<<<NWIN, THREADS, SMEM_BYTES>>>(
            din, wpb, w2pb, rpef + (size_t)blk * RPEF_BLK,
            rpe + (size_t)blk * NH * SW * SW, qkvr, attn,
            cpe_w + blk * 3 * NC, cpe_b + o1, ln1_g + o1, ln1_b + o1,
            qkv_b + o3, proj_b + o1, ln2_g + o1, ln2_b + o1,
            b1 + oh, b2 + o1, gamma1 + o1, gamma2 + o1, dout);

        const uint4* wqkv_n = (blk == 0) ? (wpall + WP_BLK + WP_QKV) : nullptr;
        post_kernel<<<128, THREADS, POST_SMEM>>>(
            rtin, attn, wpb + WP_PROJ, wpb + WP_W1, wpb + WP_W2,
            proj_b + o1, ln2_g + o1, ln2_b + o1, b1 + oh, b2 + o1,
            gamma1 + o1, gamma2 + o1, rtout,
            wqkv_n, ln1_g + NC, ln1_b + NC, qkv_b + 3 * NC, qkvr);
    }
}